// round 1
// baseline (speedup 1.0000x reference)
#include <cuda_runtime.h>
#include <cstdint>

#define BATCH 4
#define SEQL  1024
#define CH    512
#define KW    5
#define DI    1024     // d_inner
#define DS    16       // d_state
#define DTR   32       // dt_rank
#define BL    (BATCH*SEQL)
#define XZW   (2*DI)   // 2048

// ---------------- scratch (static device memory; no allocations) ----------------
__device__ float g_h[BL*CH];       // post-embedding / post-layer activations
__device__ float g_tmp[BL*CH];     // conv pre-LN
__device__ float g_xz[BL*XZW];     // in-proj output [u | z]
__device__ float g_u[BL*DI];       // depthwise-conv + silu output
__device__ float g_delta[BL*DI];   // softplus(dt @ dt_w.T + dt_b)
__device__ float g_xdbc[BL*64];    // [dt(32) | B(16) | C(16)]
__device__ float g_y[BL*DI];       // scan output (gated)
__device__ float g_comb[BL*2*CH];  // [fo | bo]

// ---------------- helpers ----------------
__device__ __forceinline__ float siluf(float x) {
    return x / (1.0f + __expf(-x));
}
__device__ __forceinline__ float softplusf(float x) {
    return fmaxf(x, 0.0f) + log1pf(__expf(-fabsf(x)));
}

// ---------------- embedding gather ----------------
__global__ void embed_k(const int* __restrict__ x, const float* __restrict__ emb,
                        float* __restrict__ out) {
    int i = blockIdx.x * blockDim.x + threadIdx.x;
    if (i >= BL * CH) return;
    int row = i >> 9;          // /512
    int c   = i & (CH - 1);
    out[i] = emb[x[row] * CH + c];
}

// ---------------- conv1d(C->C, K=5, pad=2) as implicit im2col GEMM ----------------
// Out[row, co] = bias[co] + sum_{ci,k} W[co, ci, k] * In[b, l+k-2, ci]
__global__ void conv_gemm_k(const float* __restrict__ In, const float* __restrict__ Wt,
                            const float* __restrict__ bias, float* __restrict__ Out) {
    const int KK = CH * KW; // 2560
    __shared__ float As[16][68];
    __shared__ float Ws[16][68];
    int tid  = threadIdx.x;            // 256
    int lrow = tid >> 4, lk = tid & 15;
    int tx   = tid & 15, ty = tid >> 4;
    int m0 = blockIdx.y * 64, n0 = blockIdx.x * 64;

    float acc[4][4];
#pragma unroll
    for (int i = 0; i < 4; i++)
#pragma unroll
        for (int j = 0; j < 4; j++) acc[i][j] = 0.0f;

    for (int k0 = 0; k0 < KK; k0 += 16) {
        int kidx = k0 + lk;
        int ci = kidx / KW;
        int kk = kidx - ci * KW;
#pragma unroll
        for (int i = 0; i < 4; i++) {
            int r = m0 + lrow + i * 16;
            int l = r & (SEQL - 1);
            int lp = l + kk - 2;
            float v = 0.0f;
            if (lp >= 0 && lp < SEQL) v = In[(size_t)(r - l + lp) * CH + ci];
            As[lk][lrow + i * 16] = v;
        }
#pragma unroll
        for (int i = 0; i < 4; i++) {
            int c = n0 + lrow + i * 16;
            Ws[lk][lrow + i * 16] = Wt[(size_t)c * KK + kidx];
        }
        __syncthreads();
#pragma unroll
        for (int kq = 0; kq < 16; kq++) {
            float4 av = *(const float4*)&As[kq][ty * 4];
            float4 bv = *(const float4*)&Ws[kq][tx * 4];
            float a[4] = {av.x, av.y, av.z, av.w};
            float b[4] = {bv.x, bv.y, bv.z, bv.w};
#pragma unroll
            for (int i = 0; i < 4; i++)
#pragma unroll
                for (int j = 0; j < 4; j++) acc[i][j] = fmaf(a[i], b[j], acc[i][j]);
        }
        __syncthreads();
    }
#pragma unroll
    for (int i = 0; i < 4; i++) {
        int r = m0 + ty * 4 + i;
#pragma unroll
        for (int j = 0; j < 4; j++) {
            int c = n0 + tx * 4 + j;
            Out[(size_t)r * CH + c] = acc[i][j] + bias[c];
        }
    }
}

// ---------------- channel LayerNorm + LeakyReLU(0.2) + mask ----------------
__global__ void ln_k(const float* __restrict__ In, const float* __restrict__ gamma,
                     const float* __restrict__ beta, const unsigned char* __restrict__ m,
                     float* __restrict__ Out) {
    int row = blockIdx.x;
    int t = threadIdx.x;   // 128
    float v[4];
    float s = 0.0f;
#pragma unroll
    for (int i = 0; i < 4; i++) {
        v[i] = In[(size_t)row * CH + t + i * 128];
        s += v[i];
    }
    __shared__ float sm[4];
    // reduce sum
    for (int o = 16; o > 0; o >>= 1) s += __shfl_xor_sync(~0u, s, o);
    if ((t & 31) == 0) sm[t >> 5] = s;
    __syncthreads();
    float mean = (sm[0] + sm[1] + sm[2] + sm[3]) * (1.0f / CH);
    __syncthreads();
    float s2 = 0.0f;
#pragma unroll
    for (int i = 0; i < 4; i++) {
        float d = v[i] - mean;
        s2 += d * d;
    }
    for (int o = 16; o > 0; o >>= 1) s2 += __shfl_xor_sync(~0u, s2, o);
    if ((t & 31) == 0) sm[t >> 5] = s2;
    __syncthreads();
    float var = (sm[0] + sm[1] + sm[2] + sm[3]) * (1.0f / CH);
    float rstd = rsqrtf(var + 1e-5f);
    unsigned char mm = m[row];
#pragma unroll
    for (int i = 0; i < 4; i++) {
        int c = t + i * 128;
        float h = (v[i] - mean) * rstd * gamma[c] + beta[c];
        h = (h > 0.0f) ? h : 0.2f * h;
        if (mm) h = 0.0f;
        Out[(size_t)row * CH + c] = h;
    }
}

// ---------------- generic SGEMM: Out[M,N] = A[M,K] @ W[N,K]^T ----------------
// ACT: 0 none, 1 +bias, 2 softplus(x+bias), 3 +bias then mask-zero
template <int ACT>
__global__ void gemm_k(const float* __restrict__ A, const float* __restrict__ Wt,
                       const float* __restrict__ bias, float* __restrict__ Out,
                       int M, int N, int K, int lda, int ldo, int rev,
                       const unsigned char* __restrict__ mask) {
    __shared__ float As[16][68];
    __shared__ float Ws[16][68];
    int tid  = threadIdx.x;
    int lrow = tid >> 4, lk = tid & 15;
    int tx   = tid & 15, ty = tid >> 4;
    int m0 = blockIdx.y * 64, n0 = blockIdx.x * 64;

    float acc[4][4];
#pragma unroll
    for (int i = 0; i < 4; i++)
#pragma unroll
        for (int j = 0; j < 4; j++) acc[i][j] = 0.0f;

    for (int k0 = 0; k0 < K; k0 += 16) {
        int kq = k0 + lk;
#pragma unroll
        for (int i = 0; i < 4; i++) {
            int r = m0 + lrow + i * 16;
            int ar = r;
            if (rev) ar = (r & ~(SEQL - 1)) + (SEQL - 1 - (r & (SEQL - 1)));
            float v = 0.0f;
            if (r < M && kq < K) v = A[(size_t)ar * lda + kq];
            As[lk][lrow + i * 16] = v;
        }
#pragma unroll
        for (int i = 0; i < 4; i++) {
            int c = n0 + lrow + i * 16;
            float v = 0.0f;
            if (c < N && kq < K) v = Wt[(size_t)c * K + kq];
            Ws[lk][lrow + i * 16] = v;
        }
        __syncthreads();
#pragma unroll
        for (int kk = 0; kk < 16; kk++) {
            float4 av = *(const float4*)&As[kk][ty * 4];
            float4 bv = *(const float4*)&Ws[kk][tx * 4];
            float a[4] = {av.x, av.y, av.z, av.w};
            float b[4] = {bv.x, bv.y, bv.z, bv.w};
#pragma unroll
            for (int i = 0; i < 4; i++)
#pragma unroll
                for (int j = 0; j < 4; j++) acc[i][j] = fmaf(a[i], b[j], acc[i][j]);
        }
        __syncthreads();
    }
#pragma unroll
    for (int i = 0; i < 4; i++) {
        int r = m0 + ty * 4 + i;
        if (r >= M) continue;
        unsigned char mm = (ACT == 3) ? mask[r] : 0;
#pragma unroll
        for (int j = 0; j < 4; j++) {
            int c = n0 + tx * 4 + j;
            if (c >= N) continue;
            float v = acc[i][j];
            if (ACT == 1) v += bias[c];
            if (ACT == 2) v = softplusf(v + bias[c]);
            if (ACT == 3) { v += bias[c]; if (mm) v = 0.0f; }
            Out[(size_t)r * ldo + c] = v;
        }
    }
}

// ---------------- causal depthwise conv (d_conv=4) + SiLU ----------------
__global__ void dwconv_k(const float* __restrict__ xz, const float* __restrict__ cw,
                         const float* __restrict__ cb, float* __restrict__ out) {
    int i = blockIdx.x * blockDim.x + threadIdx.x;
    if (i >= BL * DI) return;
    int d = i & (DI - 1);
    int row = i >> 10;
    int l = row & (SEQL - 1);
    float acc = cb[d];
#pragma unroll
    for (int k = 0; k < 4; k++) {
        int lp = l - 3 + k;
        if (lp >= 0) acc = fmaf(cw[d * 4 + k], xz[(size_t)(row - l + lp) * XZW + d], acc);
    }
    out[i] = siluf(acc);
}

// ---------------- selective scan + gate ----------------
// thread = (d-lane, n); warp = 2 d-values x 16 states; serial over L
__global__ void scan_k(const float* __restrict__ delta, const float* __restrict__ u,
                       const float* __restrict__ xdbc, const float* __restrict__ xz,
                       const float* __restrict__ A_log, const float* __restrict__ Dv,
                       float* __restrict__ y) {
    int t = threadIdx.x;            // 512
    int n = t & 15, dd = t >> 4;    // dd in 0..31
    int d = blockIdx.x * 32 + dd;
    int b = blockIdx.y;
    float a  = -__expf(A_log[d * DS + n]);
    float Dd = Dv[d];
    float h = 0.0f;
    int base = b * SEQL;
    for (int l = 0; l < SEQL; l++) {
        int row = base + l;
        float de = delta[(size_t)row * DI + d];
        float uu = u[(size_t)row * DI + d];
        float Bv = xdbc[row * 64 + DTR + n];
        float Cv = xdbc[row * 64 + DTR + DS + n];
        float dA = __expf(de * a);
        h = fmaf(dA, h, de * Bv * uu);
        float c = h * Cv;
        c += __shfl_xor_sync(0xffffffffu, c, 1, 16);
        c += __shfl_xor_sync(0xffffffffu, c, 2, 16);
        c += __shfl_xor_sync(0xffffffffu, c, 4, 16);
        c += __shfl_xor_sync(0xffffffffu, c, 8, 16);
        if (n == 0) {
            float z = xz[(size_t)row * XZW + DI + d];
            y[(size_t)row * DI + d] = (c + uu * Dd) * siluf(z);
        }
    }
}

// ---------------- launch ----------------
static float* symp(const void* sym) {
    void* p = nullptr;
    cudaGetSymbolAddress(&p, sym);
    return (float*)p;
}

extern "C" void kernel_launch(void* const* d_in, const int* in_sizes, int n_in,
                              void* d_out, int out_size) {
    const int*           x      = (const int*)d_in[0];
    const unsigned char* m      = (const unsigned char*)d_in[2];
    const float*         emb    = (const float*)d_in[3];
    const float*         conv_w = (const float*)d_in[4];
    const float*         conv_b = (const float*)d_in[5];
    const float*         ln_g   = (const float*)d_in[6];
    const float*         ln_b   = (const float*)d_in[7];
    const float*         proj_w = (const float*)d_in[8];
    const float*         proj_b = (const float*)d_in[9];
    float* out = (float*)d_out;

    float* h    = symp(g_h);
    float* tmp  = symp(g_tmp);
    float* xz   = symp(g_xz);
    float* u    = symp(g_u);
    float* dl   = symp(g_delta);
    float* xdbc = symp(g_xdbc);
    float* y    = symp(g_y);
    float* comb = symp(g_comb);

    embed_k<<<(BL * CH + 255) / 256, 256>>>(x, emb, h);

    for (int layer = 0; layer < 3; layer++) {
        conv_gemm_k<<<dim3(CH / 64, BL / 64), 256>>>(
            h, conv_w + (size_t)layer * CH * CH * KW, conv_b + layer * CH, tmp);
        ln_k<<<BL, 128>>>(tmp, ln_g + layer * CH, ln_b + layer * CH, m, h);
    }

    for (int dir = 0; dir < 2; dir++) {
        const float* in_w    = (const float*)d_in[10 + dir * 9 + 0];
        const float* mcw     = (const float*)d_in[10 + dir * 9 + 1];
        const float* mcb     = (const float*)d_in[10 + dir * 9 + 2];
        const float* x_w     = (const float*)d_in[10 + dir * 9 + 3];
        const float* dt_w    = (const float*)d_in[10 + dir * 9 + 4];
        const float* dt_b    = (const float*)d_in[10 + dir * 9 + 5];
        const float* A_log   = (const float*)d_in[10 + dir * 9 + 6];
        const float* Dvec    = (const float*)d_in[10 + dir * 9 + 7];
        const float* out_w   = (const float*)d_in[10 + dir * 9 + 8];
        int rev = dir;

        // xz = h(rev?) @ in_w.T   [BL, 2048]
        gemm_k<0><<<dim3(XZW / 64, BL / 64), 256>>>(h, in_w, nullptr, xz,
                                                    BL, XZW, CH, CH, XZW, rev, nullptr);
        // u = silu(dwconv(xz[:, :DI]))
        dwconv_k<<<(BL * DI + 255) / 256, 256>>>(xz, mcw, mcb, u);
        // xdbc = u @ x_w.T   [BL, 64]
        gemm_k<0><<<dim3(1, BL / 64), 256>>>(u, x_w, nullptr, xdbc,
                                             BL, 64, DI, DI, 64, 0, nullptr);
        // delta = softplus(xdbc[:, :32] @ dt_w.T + dt_b)   [BL, DI]
        gemm_k<2><<<dim3(DI / 64, BL / 64), 256>>>(xdbc, dt_w, dt_b, dl,
                                                   BL, DI, DTR, 64, DI, 0, nullptr);
        // selective scan + gate -> y
        scan_k<<<dim3(DI / 32, BATCH), 512>>>(dl, u, xdbc, xz, A_log, Dvec, y);
        // fo/bo = y @ out_w.T -> comb columns [dir*CH, dir*CH+CH)
        gemm_k<0><<<dim3(CH / 64, BL / 64), 256>>>(y, out_w, nullptr, comb + dir * CH,
                                                   BL, CH, DI, DI, 2 * CH, 0, nullptr);
    }

    // out = comb @ proj_w.T + proj_b, masked
    gemm_k<3><<<dim3(CH / 64, BL / 64), 256>>>(comb, proj_w, proj_b, out,
                                               BL, CH, 2 * CH, 2 * CH, CH, 0, m);
}

// round 2
// speedup vs baseline: 1.9898x; 1.9898x over previous
#include <cuda_runtime.h>
#include <cstdint>

#define BATCH 4
#define SEQL  1024
#define CH    512
#define KW    5
#define DI    1024     // d_inner
#define DS    16       // d_state
#define DTR   32       // dt_rank
#define BL    (BATCH*SEQL)
#define XZW   (2*DI)   // 2048

// GEMM tiling
#define BM 128
#define BN 64
#define BK 16
#define KST 20   // BK + 4 pad (row stride in floats, 80B = 16B-aligned)

// ---------------- scratch (static device memory; no allocations) ----------------
__device__ float g_h[BL*CH];
__device__ float g_tmp[BL*CH];
__device__ float g_xz[BL*XZW];
__device__ float g_u[BL*DI];
__device__ float g_delta[BL*DI];
__device__ float g_xdbc[BL*64];
__device__ float g_y[BL*DI];
__device__ float g_comb[BL*2*CH];

// ---------------- helpers ----------------
__device__ __forceinline__ float siluf(float x) { return x / (1.0f + __expf(-x)); }
__device__ __forceinline__ float softplusf(float x) {
    return fmaxf(x, 0.0f) + log1pf(__expf(-fabsf(x)));
}
__device__ __forceinline__ uint32_t f2tf(float x) {
    uint32_t r; asm("cvt.rna.tf32.f32 %0, %1;" : "=r"(r) : "f"(x)); return r;
}
__device__ __forceinline__ void mma8(float* d, const uint32_t* a, const uint32_t* b) {
    asm volatile(
        "mma.sync.aligned.m16n8k8.row.col.f32.tf32.tf32.f32 "
        "{%0,%1,%2,%3}, {%4,%5,%6,%7}, {%8,%9}, {%0,%1,%2,%3};"
        : "+f"(d[0]), "+f"(d[1]), "+f"(d[2]), "+f"(d[3])
        : "r"(a[0]), "r"(a[1]), "r"(a[2]), "r"(a[3]), "r"(b[0]), "r"(b[1]));
}
__device__ __forceinline__ void cp16(void* dst, const void* src) {
    unsigned d = (unsigned)__cvta_generic_to_shared(dst);
    asm volatile("cp.async.cg.shared.global [%0], [%1], 16;" :: "r"(d), "l"(src));
}
__device__ __forceinline__ void cpcommit() { asm volatile("cp.async.commit_group;"); }
template<int N> __device__ __forceinline__ void cpwait() {
    asm volatile("cp.async.wait_group %0;" :: "n"(N));
}

// ---------------- embedding gather ----------------
__global__ void embed_k(const int* __restrict__ x, const float* __restrict__ emb,
                        float* __restrict__ out) {
    int i = blockIdx.x * blockDim.x + threadIdx.x;
    if (i >= BL * CH) return;
    int row = i >> 9;
    int c   = i & (CH - 1);
    out[i] = emb[x[row] * CH + c];
}

// ---------------- generic tf32 MMA GEMM: Out[M,N] = A[M,K] @ W[N,K]^T ----------------
// ACT: 0 none, 1 +bias, 2 softplus(x+bias), 3 +bias then mask-zero
template <int ACT>
__global__ __launch_bounds__(256)
void mma_gemm_k(const float* __restrict__ A, const float* __restrict__ Wt,
                const float* __restrict__ bias, float* __restrict__ Out,
                int M, int N, int K, int lda, int ldo, int rev,
                const unsigned char* __restrict__ mask) {
    __shared__ float As[2][BM][KST];
    __shared__ float Bs[2][BN][KST];
    const int t = threadIdx.x;
    const int lane = t & 31, warp = t >> 5;
    const int wm = warp >> 1, wn = warp & 1;
    const int m0 = blockIdx.y * BM, n0 = blockIdx.x * BN;

    float acc[2][4][4];
#pragma unroll
    for (int i = 0; i < 2; i++)
#pragma unroll
        for (int j = 0; j < 4; j++)
#pragma unroll
            for (int q = 0; q < 4; q++) acc[i][j][q] = 0.0f;

    const int arow0 = t >> 2;          // + j*64
    const int aoff  = (t & 3) << 2;    // 0,4,8,12
    const int brow  = t >> 2;          // 0..63

    // prologue: chunk 0
    {
#pragma unroll
        for (int j = 0; j < 2; j++) {
            int row = arow0 + j * 64;
            int r = m0 + row;
            int ar = rev ? ((r & ~(SEQL - 1)) + (SEQL - 1) - (r & (SEQL - 1))) : r;
            cp16(&As[0][row][aoff], A + (size_t)ar * lda + aoff);
        }
        cp16(&Bs[0][brow][aoff], Wt + (size_t)(n0 + brow) * K + aoff);
        cpcommit();
    }
    const int nch = K >> 4;
    for (int ch = 0; ch < nch; ch++) {
        int bb = ch & 1;
        if (ch + 1 < nch) {
            int k0 = (ch + 1) << 4;
#pragma unroll
            for (int j = 0; j < 2; j++) {
                int row = arow0 + j * 64;
                int r = m0 + row;
                int ar = rev ? ((r & ~(SEQL - 1)) + (SEQL - 1) - (r & (SEQL - 1))) : r;
                cp16(&As[bb ^ 1][row][aoff], A + (size_t)ar * lda + k0 + aoff);
            }
            cp16(&Bs[bb ^ 1][brow][aoff], Wt + (size_t)(n0 + brow) * K + k0 + aoff);
            cpcommit();
            cpwait<1>();
        } else {
            cpwait<0>();
        }
        __syncthreads();
#pragma unroll
        for (int ks = 0; ks < 2; ks++) {
            int kb = ks * 8 + (lane & 3);
            uint32_t af[2][4], bf[4][2];
#pragma unroll
            for (int mf = 0; mf < 2; mf++) {
                int r = wm * 32 + mf * 16 + (lane >> 2);
                af[mf][0] = f2tf(As[bb][r][kb]);
                af[mf][1] = f2tf(As[bb][r + 8][kb]);
                af[mf][2] = f2tf(As[bb][r][kb + 4]);
                af[mf][3] = f2tf(As[bb][r + 8][kb + 4]);
            }
#pragma unroll
            for (int nf = 0; nf < 4; nf++) {
                int cn = wn * 32 + nf * 8 + (lane >> 2);
                bf[nf][0] = f2tf(Bs[bb][cn][kb]);
                bf[nf][1] = f2tf(Bs[bb][cn][kb + 4]);
            }
#pragma unroll
            for (int mf = 0; mf < 2; mf++)
#pragma unroll
                for (int nf = 0; nf < 4; nf++) mma8(acc[mf][nf], af[mf], bf[nf]);
        }
        __syncthreads();
    }
    // epilogue
#pragma unroll
    for (int mf = 0; mf < 2; mf++) {
#pragma unroll
        for (int half = 0; half < 2; half++) {
            int r = m0 + wm * 32 + mf * 16 + (lane >> 2) + half * 8;
            unsigned char mm = (ACT == 3) ? mask[r] : 0;
#pragma unroll
            for (int nf = 0; nf < 4; nf++) {
                int cn = n0 + wn * 32 + nf * 8 + ((lane & 3) << 1);
#pragma unroll
                for (int q = 0; q < 2; q++) {
                    float v = acc[mf][nf][half * 2 + q];
                    int c = cn + q;
                    if (ACT == 1) v += bias[c];
                    if (ACT == 2) v = softplusf(v + bias[c]);
                    if (ACT == 3) { v += bias[c]; if (mm) v = 0.0f; }
                    Out[(size_t)r * ldo + c] = v;
                }
            }
        }
    }
}

// ---------------- conv1d(C->C, K=5, pad=2) as implicit-im2col tf32 MMA GEMM ----------------
__global__ __launch_bounds__(256)
void mma_conv_k(const float* __restrict__ In, const float* __restrict__ Wt,
                const float* __restrict__ bias, float* __restrict__ Out) {
    const int KK = CH * KW; // 2560
    __shared__ float As[2][BM][KST];
    __shared__ float Bs[2][BN][KST];
    const int t = threadIdx.x;
    const int lane = t & 31, warp = t >> 5;
    const int wm = warp >> 1, wn = warp & 1;
    const int m0 = blockIdx.y * BM, n0 = blockIdx.x * BN;
    const int ak = t & 15, amb = t >> 4;
    const int aoff = (t & 3) << 2, brow = t >> 2;

    float acc[2][4][4];
#pragma unroll
    for (int i = 0; i < 2; i++)
#pragma unroll
        for (int j = 0; j < 4; j++)
#pragma unroll
            for (int q = 0; q < 4; q++) acc[i][j][q] = 0.0f;

    float rA[8];
    // prologue: chunk 0 A -> regs, B -> smem
    {
        int kidx = ak; int ci = kidx / KW; int kk = kidx - ci * KW;
#pragma unroll
        for (int i = 0; i < 8; i++) {
            int r = m0 + amb + i * 16;
            int l = r & (SEQL - 1);
            int lp = l + kk - 2;
            rA[i] = (lp >= 0 && lp < SEQL) ? In[(size_t)(r - l + lp) * CH + ci] : 0.0f;
        }
        cp16(&Bs[0][brow][aoff], Wt + (size_t)(n0 + brow) * KK + aoff);
        cpcommit();
    }
    const int nch = KK >> 4; // 160
    for (int ch = 0; ch < nch; ch++) {
        int bb = ch & 1;
#pragma unroll
        for (int i = 0; i < 8; i++) As[bb][amb + i * 16][ak] = rA[i];
        if (ch + 1 < nch) {
            int k0 = (ch + 1) << 4;
            int kidx = k0 + ak; int ci = kidx / KW; int kk = kidx - ci * KW;
#pragma unroll
            for (int i = 0; i < 8; i++) {
                int r = m0 + amb + i * 16;
                int l = r & (SEQL - 1);
                int lp = l + kk - 2;
                rA[i] = (lp >= 0 && lp < SEQL) ? In[(size_t)(r - l + lp) * CH + ci] : 0.0f;
            }
            cp16(&Bs[bb ^ 1][brow][aoff], Wt + (size_t)(n0 + brow) * KK + k0 + aoff);
            cpcommit();
            cpwait<1>();
        } else {
            cpwait<0>();
        }
        __syncthreads();
#pragma unroll
        for (int ks = 0; ks < 2; ks++) {
            int kb = ks * 8 + (lane & 3);
            uint32_t af[2][4], bf[4][2];
#pragma unroll
            for (int mf = 0; mf < 2; mf++) {
                int r = wm * 32 + mf * 16 + (lane >> 2);
                af[mf][0] = f2tf(As[bb][r][kb]);
                af[mf][1] = f2tf(As[bb][r + 8][kb]);
                af[mf][2] = f2tf(As[bb][r][kb + 4]);
                af[mf][3] = f2tf(As[bb][r + 8][kb + 4]);
            }
#pragma unroll
            for (int nf = 0; nf < 4; nf++) {
                int cn = wn * 32 + nf * 8 + (lane >> 2);
                bf[nf][0] = f2tf(Bs[bb][cn][kb]);
                bf[nf][1] = f2tf(Bs[bb][cn][kb + 4]);
            }
#pragma unroll
            for (int mf = 0; mf < 2; mf++)
#pragma unroll
                for (int nf = 0; nf < 4; nf++) mma8(acc[mf][nf], af[mf], bf[nf]);
        }
        __syncthreads();
    }
#pragma unroll
    for (int mf = 0; mf < 2; mf++) {
#pragma unroll
        for (int half = 0; half < 2; half++) {
            int r = m0 + wm * 32 + mf * 16 + (lane >> 2) + half * 8;
#pragma unroll
            for (int nf = 0; nf < 4; nf++) {
                int cn = n0 + wn * 32 + nf * 8 + ((lane & 3) << 1);
#pragma unroll
                for (int q = 0; q < 2; q++) {
                    Out[(size_t)r * CH + cn + q] = acc[mf][nf][half * 2 + q] + bias[cn + q];
                }
            }
        }
    }
}

// ---------------- channel LayerNorm + LeakyReLU(0.2) + mask ----------------
__global__ void ln_k(const float* __restrict__ In, const float* __restrict__ gamma,
                     const float* __restrict__ beta, const unsigned char* __restrict__ m,
                     float* __restrict__ Out) {
    int row = blockIdx.x;
    int t = threadIdx.x;   // 128
    float v[4];
    float s = 0.0f;
#pragma unroll
    for (int i = 0; i < 4; i++) {
        v[i] = In[(size_t)row * CH + t + i * 128];
        s += v[i];
    }
    __shared__ float sm[4];
    for (int o = 16; o > 0; o >>= 1) s += __shfl_xor_sync(~0u, s, o);
    if ((t & 31) == 0) sm[t >> 5] = s;
    __syncthreads();
    float mean = (sm[0] + sm[1] + sm[2] + sm[3]) * (1.0f / CH);
    __syncthreads();
    float s2 = 0.0f;
#pragma unroll
    for (int i = 0; i < 4; i++) {
        float d = v[i] - mean;
        s2 += d * d;
    }
    for (int o = 16; o > 0; o >>= 1) s2 += __shfl_xor_sync(~0u, s2, o);
    if ((t & 31) == 0) sm[t >> 5] = s2;
    __syncthreads();
    float var = (sm[0] + sm[1] + sm[2] + sm[3]) * (1.0f / CH);
    float rstd = rsqrtf(var + 1e-5f);
    unsigned char mm = m[row];
#pragma unroll
    for (int i = 0; i < 4; i++) {
        int c = t + i * 128;
        float h = (v[i] - mean) * rstd * gamma[c] + beta[c];
        h = (h > 0.0f) ? h : 0.2f * h;
        if (mm) h = 0.0f;
        Out[(size_t)row * CH + c] = h;
    }
}

// ---------------- causal depthwise conv (d_conv=4) + SiLU ----------------
__global__ void dwconv_k(const float* __restrict__ xz, const float* __restrict__ cw,
                         const float* __restrict__ cb, float* __restrict__ out) {
    int i = blockIdx.x * blockDim.x + threadIdx.x;
    if (i >= BL * DI) return;
    int d = i & (DI - 1);
    int row = i >> 10;
    int l = row & (SEQL - 1);
    float acc = cb[d];
#pragma unroll
    for (int k = 0; k < 4; k++) {
        int lp = l - 3 + k;
        if (lp >= 0) acc = fmaf(cw[d * 4 + k], xz[(size_t)(row - l + lp) * XZW + d], acc);
    }
    out[i] = siluf(acc);
}

// ---------------- selective scan + gate (software-pipelined) ----------------
__global__ void scan_k(const float* __restrict__ delta, const float* __restrict__ u,
                       const float* __restrict__ xdbc, const float* __restrict__ xz,
                       const float* __restrict__ A_log, const float* __restrict__ Dv,
                       float* __restrict__ y) {
    int t = threadIdx.x;            // 256
    int n = t & 15, dd = t >> 4;    // dd in 0..15
    int d = blockIdx.x * 16 + dd;
    int b = blockIdx.y;
    float a  = -__expf(A_log[d * DS + n]);
    float Dd = Dv[d];
    float h = 0.0f;
    int base = b * SEQL;
    // prefetch l=0
    float de = delta[(size_t)base * DI + d];
    float uu = u[(size_t)base * DI + d];
    float Bv = xdbc[base * 64 + DTR + n];
    float Cv = xdbc[base * 64 + DTR + DS + n];
    for (int l = 0; l < SEQL; l++) {
        int row = base + l;
        float de_n = 0.0f, uu_n = 0.0f, Bv_n = 0.0f, Cv_n = 0.0f;
        if (l + 1 < SEQL) {
            int rn = row + 1;
            de_n = delta[(size_t)rn * DI + d];
            uu_n = u[(size_t)rn * DI + d];
            Bv_n = xdbc[rn * 64 + DTR + n];
            Cv_n = xdbc[rn * 64 + DTR + DS + n];
        }
        float dA = __expf(de * a);
        h = fmaf(dA, h, de * Bv * uu);
        float c = h * Cv;
        c += __shfl_xor_sync(0xffffffffu, c, 1, 16);
        c += __shfl_xor_sync(0xffffffffu, c, 2, 16);
        c += __shfl_xor_sync(0xffffffffu, c, 4, 16);
        c += __shfl_xor_sync(0xffffffffu, c, 8, 16);
        if (n == 0) {
            float z = xz[(size_t)row * XZW + DI + d];
            y[(size_t)row * DI + d] = (c + uu * Dd) * siluf(z);
        }
        de = de_n; uu = uu_n; Bv = Bv_n; Cv = Cv_n;
    }
}

// ---------------- launch ----------------
static float* symp(const void* sym) {
    void* p = nullptr;
    cudaGetSymbolAddress(&p, sym);
    return (float*)p;
}

extern "C" void kernel_launch(void* const* d_in, const int* in_sizes, int n_in,
                              void* d_out, int out_size) {
    const int*           x      = (const int*)d_in[0];
    const unsigned char* m      = (const unsigned char*)d_in[2];
    const float*         emb    = (const float*)d_in[3];
    const float*         conv_w = (const float*)d_in[4];
    const float*         conv_b = (const float*)d_in[5];
    const float*         ln_g   = (const float*)d_in[6];
    const float*         ln_b   = (const float*)d_in[7];
    const float*         proj_w = (const float*)d_in[8];
    const float*         proj_b = (const float*)d_in[9];
    float* out = (float*)d_out;

    float* h    = symp(g_h);
    float* tmp  = symp(g_tmp);
    float* xz   = symp(g_xz);
    float* u    = symp(g_u);
    float* dl   = symp(g_delta);
    float* xdbc = symp(g_xdbc);
    float* y    = symp(g_y);
    float* comb = symp(g_comb);

    embed_k<<<(BL * CH + 255) / 256, 256>>>(x, emb, h);

    for (int layer = 0; layer < 3; layer++) {
        mma_conv_k<<<dim3(CH / BN, BL / BM), 256>>>(
            h, conv_w + (size_t)layer * CH * CH * KW, conv_b + layer * CH, tmp);
        ln_k<<<BL, 128>>>(tmp, ln_g + layer * CH, ln_b + layer * CH, m, h);
    }

    for (int dir = 0; dir < 2; dir++) {
        const float* in_w  = (const float*)d_in[10 + dir * 9 + 0];
        const float* mcw   = (const float*)d_in[10 + dir * 9 + 1];
        const float* mcb   = (const float*)d_in[10 + dir * 9 + 2];
        const float* x_w   = (const float*)d_in[10 + dir * 9 + 3];
        const float* dt_w  = (const float*)d_in[10 + dir * 9 + 4];
        const float* dt_b  = (const float*)d_in[10 + dir * 9 + 5];
        const float* A_log = (const float*)d_in[10 + dir * 9 + 6];
        const float* Dvec  = (const float*)d_in[10 + dir * 9 + 7];
        const float* out_w = (const float*)d_in[10 + dir * 9 + 8];
        int rev = dir;

        // xz = h(rev?) @ in_w.T   [BL, 2048]
        mma_gemm_k<0><<<dim3(XZW / BN, BL / BM), 256>>>(h, in_w, nullptr, xz,
                                                        BL, XZW, CH, CH, XZW, rev, nullptr);
        // u = silu(dwconv(xz[:, :DI]))
        dwconv_k<<<(BL * DI + 255) / 256, 256>>>(xz, mcw, mcb, u);
        // xdbc = u @ x_w.T   [BL, 64]
        mma_gemm_k<0><<<dim3(1, BL / BM), 256>>>(u, x_w, nullptr, xdbc,
                                                 BL, 64, DI, DI, 64, 0, nullptr);
        // delta = softplus(xdbc[:, :32] @ dt_w.T + dt_b)   [BL, DI]
        mma_gemm_k<2><<<dim3(DI / BN, BL / BM), 256>>>(xdbc, dt_w, dt_b, dl,
                                                       BL, DI, DTR, 64, DI, 0, nullptr);
        // selective scan + gate -> y
        scan_k<<<dim3(DI / 16, BATCH), 256>>>(dl, u, xdbc, xz, A_log, Dvec, y);
        // fo/bo = y @ out_w.T -> comb columns [dir*CH, dir*CH+CH)
        mma_gemm_k<0><<<dim3(CH / BN, BL / BM), 256>>>(y, out_w, nullptr, comb + dir * CH,
                                                       BL, CH, DI, DI, 2 * CH, 0, nullptr);
    }

    // out = comb @ proj_w.T + proj_b, masked
    mma_gemm_k<3><<<dim3(CH / BN, BL / BM), 256>>>(comb, proj_w, proj_b, out,
                                                   BL, CH, 2 * CH, 2 * CH, CH, 0, m);
}

// round 3
// speedup vs baseline: 2.5047x; 1.2588x over previous
#include <cuda_runtime.h>
#include <cuda_bf16.h>
#include <cstdint>

#define BATCH 4
#define SEQL  1024
#define CH    512
#define KW    5
#define DI    1024
#define DS    16
#define DTR   32
#define BL    (BATCH*SEQL)
#define XZW   (2*DI)

#define BM 128
#define BN 64
#define BK 32
#define KST 40   // BK + 8 pad (bf16 elems); 80B row stride, 16B aligned

typedef __nv_bfloat16 bf;

// ---------------- scratch ----------------
__device__ bf    g_h[BL*CH];
__device__ float g_tmp[BL*CH];
__device__ bf    g_xz[BL*XZW];
__device__ bf    g_u[BL*DI];
__device__ float g_delta[BL*DI];
__device__ float g_xdbc[BL*64];
__device__ bf    g_y[BL*DI];
__device__ bf    g_comb[BL*2*CH];
// converted weights
__device__ bf    g_cwt[3*KW*CH*CH];      // [layer][k][co][ci]
__device__ bf    g_inw[2][XZW*CH];
__device__ bf    g_xw[2][64*DI];
__device__ bf    g_outw[2][CH*DI];
__device__ bf    g_projw[CH*2*CH];

// ---------------- helpers ----------------
__device__ __forceinline__ float siluf(float x) { return x / (1.0f + __expf(-x)); }
__device__ __forceinline__ float softplusf(float x) {
    return fmaxf(x, 0.0f) + log1pf(__expf(-fabsf(x)));
}
__device__ __forceinline__ void cp16u(uint32_t d, const void* s) {
    asm volatile("cp.async.cg.shared.global [%0], [%1], 16;" :: "r"(d), "l"(s));
}
__device__ __forceinline__ void cp16z(uint32_t d, const void* s, int valid) {
    int sz = valid ? 16 : 0;
    asm volatile("cp.async.cg.shared.global [%0], [%1], 16, %2;" :: "r"(d), "l"(s), "r"(sz));
}
__device__ __forceinline__ void cpcommit() { asm volatile("cp.async.commit_group;"); }
template<int N> __device__ __forceinline__ void cpwait() {
    asm volatile("cp.async.wait_group %0;" :: "n"(N));
}
__device__ __forceinline__ void ldsm4(uint32_t* r, uint32_t a) {
    asm volatile("ldmatrix.sync.aligned.m8n8.x4.shared.b16 {%0,%1,%2,%3}, [%4];"
        : "=r"(r[0]), "=r"(r[1]), "=r"(r[2]), "=r"(r[3]) : "r"(a));
}
__device__ __forceinline__ void mma16(float* d, const uint32_t* a, const uint32_t* b) {
    asm volatile(
        "mma.sync.aligned.m16n8k16.row.col.f32.bf16.bf16.f32 "
        "{%0,%1,%2,%3}, {%4,%5,%6,%7}, {%8,%9}, {%0,%1,%2,%3};"
        : "+f"(d[0]), "+f"(d[1]), "+f"(d[2]), "+f"(d[3])
        : "r"(a[0]), "r"(a[1]), "r"(a[2]), "r"(a[3]), "r"(b[0]), "r"(b[1]));
}

// ---------------- weight conversion ----------------
__global__ void convT_k(const float* __restrict__ w) {
    int blk = blockIdx.x;             // layer*512 + co
    int co = blk & 511, layer = blk >> 9;
    __shared__ float s[CH*KW];
    const float* src = w + (size_t)blk * (CH*KW);
    for (int i = threadIdx.x; i < CH*KW; i += 256) s[i] = src[i];
    __syncthreads();
    bf* dst = g_cwt + (size_t)layer * KW * CH * CH;
    for (int i = threadIdx.x; i < CH*KW; i += 256) {
        int k = i >> 9, ci = i & 511;
        dst[(size_t)k*CH*CH + (size_t)co*CH + ci] = __float2bfloat16(s[ci*KW + k]);
    }
}
__global__ void f2bf_k(const float* __restrict__ in, bf* __restrict__ out, int n4) {
    int i = blockIdx.x * blockDim.x + threadIdx.x;
    if (i >= n4) return;
    float4 v = ((const float4*)in)[i];
    __nv_bfloat162* o = (__nv_bfloat162*)out;
    o[i*2]   = __floats2bfloat162_rn(v.x, v.y);
    o[i*2+1] = __floats2bfloat162_rn(v.z, v.w);
}

// ---------------- embedding ----------------
__global__ void embed_k(const int* __restrict__ x, const float* __restrict__ emb,
                        bf* __restrict__ out) {
    int i = blockIdx.x * blockDim.x + threadIdx.x;
    if (i >= BL * CH) return;
    int row = i >> 9, c = i & (CH - 1);
    out[i] = __float2bfloat16(emb[x[row] * CH + c]);
}

// ---------------- generic bf16 MMA GEMM: Out[M,N] = A[M,K] @ W[N,K]^T ----------------
// EPI: 0 bf16 out, 1 fp32 out, 2 fp32 + bias + mask
template <int EPI>
__global__ __launch_bounds__(256)
void gemm_bf(const bf* __restrict__ A, const bf* __restrict__ Wt,
             const float* __restrict__ bias, void* __restrict__ OutV,
             int M, int N, int K, int lda, int ldo, int rev,
             const unsigned char* __restrict__ mask) {
    __shared__ __align__(16) bf As[2][BM][KST];
    __shared__ __align__(16) bf Bs[2][BN][KST];
    const int t = threadIdx.x, lane = t & 31, warp = t >> 5;
    const int wm = warp >> 1, wn = warp & 1;
    const int m0 = blockIdx.y * BM, n0 = blockIdx.x * BN;

    float acc[2][4][4];
#pragma unroll
    for (int i = 0; i < 2; i++)
#pragma unroll
        for (int j = 0; j < 4; j++)
#pragma unroll
            for (int q = 0; q < 4; q++) acc[i][j][q] = 0.0f;

    const int lrowA = t >> 2;        // 0..63 (+64)
    const int koff  = (t & 3) * 8;   // bf16 elems
    int ga0, ga1;
    {
        int r = m0 + lrowA;
        ga0 = rev ? ((r & ~(SEQL-1)) + (SEQL-1) - (r & (SEQL-1))) : r;
        r = m0 + lrowA + 64;
        ga1 = rev ? ((r & ~(SEQL-1)) + (SEQL-1) - (r & (SEQL-1))) : r;
    }
    uint32_t asb = (uint32_t)__cvta_generic_to_shared(&As[0][0][0]);
    uint32_t bsb = (uint32_t)__cvta_generic_to_shared(&Bs[0][0][0]);
    const int ABUF = BM*KST*2, BBUF = BN*KST*2;
    const uint32_t a_st0 = asb + (lrowA)        * (KST*2) + koff*2;
    const uint32_t a_st1 = asb + (lrowA + 64)   * (KST*2) + koff*2;
    const uint32_t b_st  = bsb + (t >> 2)       * (KST*2) + koff*2;

    // ldmatrix per-thread offsets (bytes within a buffer)
    const uint32_t a_off = ((wm*32 + ((lane>>3)&1)*8 + (lane&7)) * KST + (lane>>4)*8) * 2;
    const uint32_t b_off = ((wn*32 + ((lane>>4)&1)*8 + (lane&7)) * KST + ((lane>>3)&1)*8) * 2;

    // prologue
    cp16u(a_st0, A + (size_t)ga0*lda + koff);
    cp16u(a_st1, A + (size_t)ga1*lda + koff);
    cp16u(b_st,  Wt + (size_t)(n0 + (t>>2))*K + koff);
    cpcommit();

    const int nch = K >> 5;
    for (int ch = 0; ch < nch; ch++) {
        int bb = ch & 1;
        if (ch + 1 < nch) {
            int k0 = (ch + 1) << 5;
            cp16u(a_st0 + (bb^1)*ABUF, A + (size_t)ga0*lda + k0 + koff);
            cp16u(a_st1 + (bb^1)*ABUF, A + (size_t)ga1*lda + k0 + koff);
            cp16u(b_st  + (bb^1)*BBUF, Wt + (size_t)(n0 + (t>>2))*K + k0 + koff);
            cpcommit();
            cpwait<1>();
        } else {
            cpwait<0>();
        }
        __syncthreads();
        uint32_t ab = asb + bb*ABUF - asb + (asb);  // = asb + bb*ABUF
        ab = asb + bb*ABUF;
        uint32_t bbase = bsb + bb*BBUF;
#pragma unroll
        for (int ks = 0; ks < 2; ks++) {
            uint32_t af[2][4], bfr[2][4];
            ldsm4(af[0], ab + (a_off - asb) + asb - asb + a_off + ks*32 - a_off + (ab - ab));  // placeholder fix below
            // (recomputed cleanly:)
            af[0][0] = 0; // overwritten
            ldsm4(af[0], (asb + bb*ABUF) + a_off + ks*32);
            ldsm4(af[1], (asb + bb*ABUF) + a_off + 16*KST*2 + ks*32);
            ldsm4(bfr[0], (bsb + bb*BBUF) + b_off + ks*32);
            ldsm4(bfr[1], (bsb + bb*BBUF) + b_off + 16*KST*2 + ks*32);
#pragma unroll
            for (int mf = 0; mf < 2; mf++)
#pragma unroll
                for (int nf = 0; nf < 4; nf++)
                    mma16(acc[mf][nf], af[mf], &bfr[nf>>1][(nf&1)*2]);
        }
        __syncthreads();
    }
    // epilogue
#pragma unroll
    for (int mf = 0; mf < 2; mf++) {
#pragma unroll
        for (int half = 0; half < 2; half++) {
            int r = m0 + wm*32 + mf*16 + (lane>>2) + half*8;
            unsigned char mm = (EPI == 2) ? mask[r] : 0;
#pragma unroll
            for (int nf = 0; nf < 4; nf++) {
                int c = n0 + wn*32 + nf*8 + (lane&3)*2;
                float v0 = acc[mf][nf][half*2], v1 = acc[mf][nf][half*2+1];
                if (EPI == 0) {
                    *(__nv_bfloat162*)((bf*)OutV + (size_t)r*ldo + c) =
                        __floats2bfloat162_rn(v0, v1);
                } else if (EPI == 1) {
                    float2 f = {v0, v1};
                    *(float2*)((float*)OutV + (size_t)r*ldo + c) = f;
                } else {
                    v0 += bias[c]; v1 += bias[c+1];
                    if (mm) { v0 = 0.0f; v1 = 0.0f; }
                    float2 f = {v0, v1};
                    *(float2*)((float*)OutV + (size_t)r*ldo + c) = f;
                }
            }
        }
    }
}

// ---------------- conv1d as shifted-row bf16 GEMM (weights pre-transposed) ----------------
__global__ __launch_bounds__(256)
void conv_bf(const bf* __restrict__ In, const bf* __restrict__ Wl,
             const float* __restrict__ bias, float* __restrict__ Out) {
    __shared__ __align__(16) bf As[2][BM][KST];
    __shared__ __align__(16) bf Bs[2][BN][KST];
    const int t = threadIdx.x, lane = t & 31, warp = t >> 5;
    const int wm = warp >> 1, wn = warp & 1;
    const int m0 = blockIdx.y * BM, n0 = blockIdx.x * BN;

    float acc[2][4][4];
#pragma unroll
    for (int i = 0; i < 2; i++)
#pragma unroll
        for (int j = 0; j < 4; j++)
#pragma unroll
            for (int q = 0; q < 4; q++) acc[i][j][q] = 0.0f;

    const int lrowA = t >> 2;
    const int koff  = (t & 3) * 8;
    const int gr0 = m0 + lrowA, gr1 = m0 + lrowA + 64;
    const int l0 = gr0 & (SEQL-1), l1 = gr1 & (SEQL-1);

    uint32_t asb = (uint32_t)__cvta_generic_to_shared(&As[0][0][0]);
    uint32_t bsb = (uint32_t)__cvta_generic_to_shared(&Bs[0][0][0]);
    const int ABUF = BM*KST*2, BBUF = BN*KST*2;
    const uint32_t a_st0 = asb + lrowA      * (KST*2) + koff*2;
    const uint32_t a_st1 = asb + (lrowA+64) * (KST*2) + koff*2;
    const uint32_t b_st  = bsb + (t>>2)     * (KST*2) + koff*2;
    const uint32_t a_off = ((wm*32 + ((lane>>3)&1)*8 + (lane&7)) * KST + (lane>>4)*8) * 2;
    const uint32_t b_off = ((wn*32 + ((lane>>4)&1)*8 + (lane&7)) * KST + ((lane>>3)&1)*8) * 2;

    auto loadA = [&](int bb, int ch) {
        int kk = ch >> 4, ci0 = (ch & 15) << 5;
        int sh = kk - 2;
        int v0 = (unsigned)(l0 + sh) < (unsigned)SEQL;
        int v1 = (unsigned)(l1 + sh) < (unsigned)SEQL;
        int rr0 = v0 ? gr0 + sh : gr0;
        int rr1 = v1 ? gr1 + sh : gr1;
        cp16z(a_st0 + bb*ABUF, In + (size_t)rr0*CH + ci0 + koff, v0);
        cp16z(a_st1 + bb*ABUF, In + (size_t)rr1*CH + ci0 + koff, v1);
        cp16u(b_st  + bb*BBUF,
              Wl + ((size_t)kk*CH + n0 + (t>>2))*CH + ci0 + koff);
    };

    loadA(0, 0);
    cpcommit();
    const int nch = KW * (CH/BK);   // 80
    for (int ch = 0; ch < nch; ch++) {
        int bb = ch & 1;
        if (ch + 1 < nch) { loadA(bb^1, ch+1); cpcommit(); cpwait<1>(); }
        else cpwait<0>();
        __syncthreads();
#pragma unroll
        for (int ks = 0; ks < 2; ks++) {
            uint32_t af[2][4], bfr[2][4];
            ldsm4(af[0], (asb + bb*ABUF) + a_off + ks*32);
            ldsm4(af[1], (asb + bb*ABUF) + a_off + 16*KST*2 + ks*32);
            ldsm4(bfr[0], (bsb + bb*BBUF) + b_off + ks*32);
            ldsm4(bfr[1], (bsb + bb*BBUF) + b_off + 16*KST*2 + ks*32);
#pragma unroll
            for (int mf = 0; mf < 2; mf++)
#pragma unroll
                for (int nf = 0; nf < 4; nf++)
                    mma16(acc[mf][nf], af[mf], &bfr[nf>>1][(nf&1)*2]);
        }
        __syncthreads();
    }
#pragma unroll
    for (int mf = 0; mf < 2; mf++) {
#pragma unroll
        for (int half = 0; half < 2; half++) {
            int r = m0 + wm*32 + mf*16 + (lane>>2) + half*8;
#pragma unroll
            for (int nf = 0; nf < 4; nf++) {
                int c = n0 + wn*32 + nf*8 + (lane&3)*2;
                float2 f = {acc[mf][nf][half*2] + bias[c],
                            acc[mf][nf][half*2+1] + bias[c+1]};
                *(float2*)(Out + (size_t)r*CH + c) = f;
            }
        }
    }
}

// ---------------- channel LayerNorm + LeakyReLU + mask (fp32 in, bf16 out) ----------------
__global__ void ln_k(const float* __restrict__ In, const float* __restrict__ gamma,
                     const float* __restrict__ beta, const unsigned char* __restrict__ m,
                     bf* __restrict__ Out) {
    int row = blockIdx.x;
    int t = threadIdx.x;   // 128
    float v[4];
    float s = 0.0f;
#pragma unroll
    for (int i = 0; i < 4; i++) {
        v[i] = In[(size_t)row * CH + t + i * 128];
        s += v[i];
    }
    __shared__ float sm[4];
    for (int o = 16; o > 0; o >>= 1) s += __shfl_xor_sync(~0u, s, o);
    if ((t & 31) == 0) sm[t >> 5] = s;
    __syncthreads();
    float mean = (sm[0] + sm[1] + sm[2] + sm[3]) * (1.0f / CH);
    __syncthreads();
    float s2 = 0.0f;
#pragma unroll
    for (int i = 0; i < 4; i++) { float d = v[i] - mean; s2 += d * d; }
    for (int o = 16; o > 0; o >>= 1) s2 += __shfl_xor_sync(~0u, s2, o);
    if ((t & 31) == 0) sm[t >> 5] = s2;
    __syncthreads();
    float var = (sm[0] + sm[1] + sm[2] + sm[3]) * (1.0f / CH);
    float rstd = rsqrtf(var + 1e-5f);
    unsigned char mm = m[row];
#pragma unroll
    for (int i = 0; i < 4; i++) {
        int c = t + i * 128;
        float h = (v[i] - mean) * rstd * gamma[c] + beta[c];
        h = (h > 0.0f) ? h : 0.2f * h;
        if (mm) h = 0.0f;
        Out[(size_t)row * CH + c] = __float2bfloat16(h);
    }
}

// ---------------- causal depthwise conv + SiLU (bf16 in/out) ----------------
__global__ void dwconv_k(const bf* __restrict__ xz, const float* __restrict__ cw,
                         const float* __restrict__ cb, bf* __restrict__ out) {
    int i = blockIdx.x * blockDim.x + threadIdx.x;
    if (i >= BL * DI) return;
    int d = i & (DI - 1);
    int row = i >> 10;
    int l = row & (SEQL - 1);
    float acc = cb[d];
#pragma unroll
    for (int k = 0; k < 4; k++) {
        int lp = l - 3 + k;
        if (lp >= 0)
            acc = fmaf(cw[d*4 + k], __bfloat162float(xz[(size_t)(row - l + lp)*XZW + d]), acc);
    }
    out[i] = __float2bfloat16(siluf(acc));
}

// ---------------- delta = softplus(xdbc[:, :32] @ dt_w.T + dt_b) ----------------
__global__ __launch_bounds__(256)
void dt_k(const float* __restrict__ xdbc, const float* __restrict__ dt_w,
          const float* __restrict__ dt_b, float* __restrict__ delta) {
    __shared__ float xs[32][32];
    int t = threadIdx.x;
    int d0 = blockIdx.x * 256, m0 = blockIdx.y * 32;
    // load xdbc tile
#pragma unroll
    for (int i = 0; i < 4; i++) {
        int idx = t + i * 256;
        xs[idx >> 5][idx & 31] = xdbc[(size_t)(m0 + (idx >> 5)) * 64 + (idx & 31)];
    }
    int d = d0 + t;
    float4 wr[8];
#pragma unroll
    for (int j = 0; j < 8; j++) wr[j] = *(const float4*)(dt_w + (size_t)d*DTR + j*4);
    float b = dt_b[d];
    __syncthreads();
#pragma unroll 4
    for (int row = 0; row < 32; row++) {
        float acc = b;
#pragma unroll
        for (int j = 0; j < 8; j++) {
            float4 x4 = *(const float4*)&xs[row][j*4];
            acc = fmaf(wr[j].x, x4.x, acc);
            acc = fmaf(wr[j].y, x4.y, acc);
            acc = fmaf(wr[j].z, x4.z, acc);
            acc = fmaf(wr[j].w, x4.w, acc);
        }
        delta[(size_t)(m0 + row) * DI + d] = softplusf(acc);
    }
}

// ---------------- selective scan + gate ----------------
__global__ void scan_k(const float* __restrict__ delta, const bf* __restrict__ u,
                       const float* __restrict__ xdbc, const bf* __restrict__ xz,
                       const float* __restrict__ A_log, const float* __restrict__ Dv,
                       bf* __restrict__ y) {
    int t = threadIdx.x;            // 256
    int n = t & 15, dd = t >> 4;
    int d = blockIdx.x * 16 + dd;
    int b = blockIdx.y;
    float a  = -__expf(A_log[d * DS + n]);
    float Dd = Dv[d];
    float h = 0.0f;
    int base = b * SEQL;
    float de = delta[(size_t)base * DI + d];
    float uu = __bfloat162float(u[(size_t)base * DI + d]);
    float Bv = xdbc[base * 64 + DTR + n];
    float Cv = xdbc[base * 64 + DTR + DS + n];
    for (int l = 0; l < SEQL; l++) {
        int row = base + l;
        float de_n = 0.0f, uu_n = 0.0f, Bv_n = 0.0f, Cv_n = 0.0f;
        if (l + 1 < SEQL) {
            int rn = row + 1;
            de_n = delta[(size_t)rn * DI + d];
            uu_n = __bfloat162float(u[(size_t)rn * DI + d]);
            Bv_n = xdbc[rn * 64 + DTR + n];
            Cv_n = xdbc[rn * 64 + DTR + DS + n];
        }
        float dA = __expf(de * a);
        h = fmaf(dA, h, de * Bv * uu);
        float c = h * Cv;
        c += __shfl_xor_sync(0xffffffffu, c, 1, 16);
        c += __shfl_xor_sync(0xffffffffu, c, 2, 16);
        c += __shfl_xor_sync(0xffffffffu, c, 4, 16);
        c += __shfl_xor_sync(0xffffffffu, c, 8, 16);
        if (n == 0) {
            float z = __bfloat162float(xz[(size_t)row * XZW + DI + d]);
            y[(size_t)row * DI + d] = __float2bfloat16((c + uu * Dd) * siluf(z));
        }
        de = de_n; uu = uu_n; Bv = Bv_n; Cv = Cv_n;
    }
}

// ---------------- launch ----------------
template <typename T>
static T* symp(const void* sym) {
    void* p = nullptr;
    cudaGetSymbolAddress(&p, sym);
    return (T*)p;
}

extern "C" void kernel_launch(void* const* d_in, const int* in_sizes, int n_in,
                              void* d_out, int out_size) {
    const int*           x      = (const int*)d_in[0];
    const unsigned char* m      = (const unsigned char*)d_in[2];
    const float*         emb    = (const float*)d_in[3];
    const float*         conv_w = (const float*)d_in[4];
    const float*         conv_b = (const float*)d_in[5];
    const float*         ln_g   = (const float*)d_in[6];
    const float*         ln_b   = (const float*)d_in[7];
    const float*         proj_w = (const float*)d_in[8];
    const float*         proj_b = (const float*)d_in[9];
    float* out = (float*)d_out;

    bf*    h    = symp<bf>(g_h);
    float* tmp  = symp<float>(g_tmp);
    bf*    xz   = symp<bf>(g_xz);
    bf*    u    = symp<bf>(g_u);
    float* dl   = symp<float>(g_delta);
    float* xdbc = symp<float>(g_xdbc);
    bf*    y    = symp<bf>(g_y);
    bf*    comb = symp<bf>(g_comb);
    bf*    cwt  = symp<bf>(g_cwt);
    bf*    inw  = symp<bf>(g_inw);
    bf*    xw   = symp<bf>(g_xw);
    bf*    outw = symp<bf>(g_outw);
    bf*    prw  = symp<bf>(g_projw);

    // weight conversions
    convT_k<<<3*CH, 256>>>(conv_w);
    for (int dir = 0; dir < 2; dir++) {
        const float* in_w  = (const float*)d_in[10 + dir*9 + 0];
        const float* x_w   = (const float*)d_in[10 + dir*9 + 3];
        const float* out_w = (const float*)d_in[10 + dir*9 + 8];
        f2bf_k<<<(XZW*CH/4 + 255)/256, 256>>>(in_w,  inw  + (size_t)dir*XZW*CH, XZW*CH/4);
        f2bf_k<<<(64*DI/4  + 255)/256, 256>>>(x_w,   xw   + (size_t)dir*64*DI,  64*DI/4);
        f2bf_k<<<(CH*DI/4  + 255)/256, 256>>>(out_w, outw + (size_t)dir*CH*DI,  CH*DI/4);
    }
    f2bf_k<<<(CH*2*CH/4 + 255)/256, 256>>>(proj_w, prw, CH*2*CH/4);

    embed_k<<<(BL*CH + 255)/256, 256>>>(x, emb, h);

    for (int layer = 0; layer < 3; layer++) {
        conv_bf<<<dim3(CH/BN, BL/BM), 256>>>(
            h, cwt + (size_t)layer*KW*CH*CH, conv_b + layer*CH, tmp);
        ln_k<<<BL, 128>>>(tmp, ln_g + layer*CH, ln_b + layer*CH, m, h);
    }

    for (int dir = 0; dir < 2; dir++) {
        const float* mcw   = (const float*)d_in[10 + dir*9 + 1];
        const float* mcb   = (const float*)d_in[10 + dir*9 + 2];
        const float* dt_w  = (const float*)d_in[10 + dir*9 + 4];
        const float* dt_b  = (const float*)d_in[10 + dir*9 + 5];
        const float* A_log = (const float*)d_in[10 + dir*9 + 6];
        const float* Dvec  = (const float*)d_in[10 + dir*9 + 7];

        gemm_bf<0><<<dim3(XZW/BN, BL/BM), 256>>>(h, inw + (size_t)dir*XZW*CH, nullptr, xz,
                                                 BL, XZW, CH, CH, XZW, dir, nullptr);
        dwconv_k<<<(BL*DI + 255)/256, 256>>>(xz, mcw, mcb, u);
        gemm_bf<1><<<dim3(1, BL/BM), 256>>>(u, xw + (size_t)dir*64*DI, nullptr, xdbc,
                                            BL, 64, DI, DI, 64, 0, nullptr);
        dt_k<<<dim3(DI/256, BL/32), 256>>>(xdbc, dt_w, dt_b, dl);
        scan_k<<<dim3(DI/16, BATCH), 256>>>(dl, u, xdbc, xz, A_log, Dvec, y);
        gemm_bf<0><<<dim3(CH/BN, BL/BM), 256>>>(y, outw + (size_t)dir*CH*DI, nullptr,
                                                comb + dir*CH,
                                                BL, CH, DI, DI, 2*CH, 0, nullptr);
    }

    gemm_bf<2><<<dim3(CH/BN, BL/BM), 256>>>(comb, prw, proj_b, out,
                                            BL, CH, 2*CH, 2*CH, CH, 0, m);
}

// round 4
// speedup vs baseline: 3.5211x; 1.4058x over previous
#include <cuda_runtime.h>
#include <cuda_bf16.h>
#include <cstdint>

#define BATCH 4
#define SEQL  1024
#define CH    512
#define KW    5
#define DI    1024
#define DS    16
#define DTR   32
#define BL    (BATCH*SEQL)
#define XZW   (2*DI)

#define BM 128
#define BK 32
#define KST 40   // BK + 8 pad (bf16 elems)

typedef __nv_bfloat16 bf;

// ---------------- scratch ----------------
__device__ bf    g_h[BL*CH];
__device__ float g_tmp[BL*CH];
__device__ bf    g_xz[2ull*BL*XZW];
__device__ bf    g_u[2ull*BL*DI];
__device__ float g_delta[2ull*BL*DI];
__device__ float g_xdbc[2ull*BL*64];
__device__ bf    g_y[2ull*BL*DI];
__device__ bf    g_comb[BL*2*CH];
__device__ bf    g_cwt[3ull*KW*CH*CH];     // [layer][k][co][ci]
__device__ bf    g_inw[2ull*XZW*CH];
__device__ bf    g_xw[2ull*64*DI];
__device__ bf    g_outw[2ull*CH*DI];
__device__ bf    g_projw[(size_t)CH*2*CH];

// ---------------- helpers ----------------
__device__ __forceinline__ float siluf(float x) { return x / (1.0f + __expf(-x)); }
__device__ __forceinline__ float softplusf(float x) {
    return fmaxf(x, 0.0f) + log1pf(__expf(-fabsf(x)));
}
__device__ __forceinline__ void cp16u(uint32_t d, const void* s) {
    asm volatile("cp.async.cg.shared.global [%0], [%1], 16;" :: "r"(d), "l"(s));
}
__device__ __forceinline__ void cp16z(uint32_t d, const void* s, int valid) {
    int sz = valid ? 16 : 0;
    asm volatile("cp.async.cg.shared.global [%0], [%1], 16, %2;" :: "r"(d), "l"(s), "r"(sz));
}
__device__ __forceinline__ void cpcommit() { asm volatile("cp.async.commit_group;"); }
template<int N> __device__ __forceinline__ void cpwait() {
    asm volatile("cp.async.wait_group %0;" :: "n"(N));
}
__device__ __forceinline__ void ldsm4(uint32_t* r, uint32_t a) {
    asm volatile("ldmatrix.sync.aligned.m8n8.x4.shared.b16 {%0,%1,%2,%3}, [%4];"
        : "=r"(r[0]), "=r"(r[1]), "=r"(r[2]), "=r"(r[3]) : "r"(a));
}
__device__ __forceinline__ void mma16(float* d, const uint32_t* a, const uint32_t* b) {
    asm volatile(
        "mma.sync.aligned.m16n8k16.row.col.f32.bf16.bf16.f32 "
        "{%0,%1,%2,%3}, {%4,%5,%6,%7}, {%8,%9}, {%0,%1,%2,%3};"
        : "+f"(d[0]), "+f"(d[1]), "+f"(d[2]), "+f"(d[3])
        : "r"(a[0]), "r"(a[1]), "r"(a[2]), "r"(a[3]), "r"(b[0]), "r"(b[1]));
}

// ---------------- weight conversion ----------------
__global__ void convT_k(const float* __restrict__ w) {
    int blk = blockIdx.x;             // layer*512 + co
    int co = blk & 511, layer = blk >> 9;
    __shared__ float s[CH*KW];
    const float* src = w + (size_t)blk * (CH*KW);
    for (int i = threadIdx.x; i < CH*KW; i += 256) s[i] = src[i];
    __syncthreads();
    bf* dst = g_cwt + (size_t)layer * KW * CH * CH;
    for (int i = threadIdx.x; i < CH*KW; i += 256) {
        int k = i >> 9, ci = i & 511;
        dst[(size_t)k*CH*CH + (size_t)co*CH + ci] = __float2bfloat16(s[ci*KW + k]);
    }
}

struct CvtP { const float* s[7]; bf* d[7]; };
__global__ void f2bf_all(CvtP p) {
    const int sz[7] = {262144, 262144, 16384, 16384, 131072, 131072, 131072};
    int i = blockIdx.x * 256 + threadIdx.x;
    int seg = 0;
#pragma unroll
    for (int s = 0; s < 7; s++) {
        if (seg == s && i >= sz[s]) { i -= sz[s]; seg = s + 1; }
    }
    if (seg >= 7) return;
    float4 v = ((const float4*)p.s[seg])[i];
    __nv_bfloat162* o = (__nv_bfloat162*)p.d[seg];
    o[i*2]   = __floats2bfloat162_rn(v.x, v.y);
    o[i*2+1] = __floats2bfloat162_rn(v.z, v.w);
}

// ---------------- embedding ----------------
__global__ void embed_k(const int* __restrict__ x, const float* __restrict__ emb,
                        bf* __restrict__ out) {
    int i = blockIdx.x * blockDim.x + threadIdx.x;
    if (i >= BL * CH) return;
    int row = i >> 9, c = i & (CH - 1);
    out[i] = __float2bfloat16(emb[x[row] * CH + c]);
}

// ---------------- generic bf16 MMA GEMM (dir-batched via blockIdx.z) ----------------
// Out[BM-tile, BNT-tile] = A[M,K] @ W[N,K]^T
// EPI: 0 bf16 out, 1 fp32 out, 2 fp32 + bias + mask
template <int BNT, int EPI>
__global__ __launch_bounds__(256, (BNT == 128) ? 2 : 3)
void gemm_bf(const bf* __restrict__ A, const bf* __restrict__ Wt,
             const float* __restrict__ bias, void* __restrict__ OutV,
             int K, int lda, int ldo, int revz,
             const unsigned char* __restrict__ mask,
             size_t az, size_t wz, size_t oz) {
    constexpr int NWN = BNT / 32;       // warps along N
    constexpr int NWM = 8 / NWN;        // warps along M
    constexpr int WTM = BM / NWM;       // rows per warp
    constexpr int MF  = WTM / 16;
    __shared__ __align__(16) bf As[2][BM][KST];
    __shared__ __align__(16) bf Bs[2][BNT][KST];
    const int t = threadIdx.x, lane = t & 31, warp = t >> 5;
    const int wm = warp / NWN, wn = warp % NWN;
    const int m0 = blockIdx.y * BM, n0 = blockIdx.x * BNT;
    const int dir = blockIdx.z;
    A  += (size_t)dir * az;
    Wt += (size_t)dir * wz;
    const int rev = revz && dir;

    float acc[MF][4][4];
#pragma unroll
    for (int i = 0; i < MF; i++)
#pragma unroll
        for (int j = 0; j < 4; j++)
#pragma unroll
            for (int q = 0; q < 4; q++) acc[i][j][q] = 0.0f;

    const int lrowA = t >> 2;
    const int koff  = (t & 3) * 8;
    int ga0, ga1;
    {
        int r = m0 + lrowA;
        ga0 = rev ? ((r & ~(SEQL-1)) + (SEQL-1) - (r & (SEQL-1))) : r;
        r = m0 + lrowA + 64;
        ga1 = rev ? ((r & ~(SEQL-1)) + (SEQL-1) - (r & (SEQL-1))) : r;
    }
    uint32_t asb = (uint32_t)__cvta_generic_to_shared(&As[0][0][0]);
    uint32_t bsb = (uint32_t)__cvta_generic_to_shared(&Bs[0][0][0]);
    const int ABUF = BM*KST*2, BBUF = BNT*KST*2;
    const uint32_t a_st0 = asb + lrowA * (KST*2) + koff*2;
    const uint32_t a_st1 = a_st0 + 64 * (KST*2);
    const uint32_t b_st0 = bsb + (t >> 2) * (KST*2) + koff*2;
    const uint32_t a_off = ((wm*WTM + ((lane>>3)&1)*8 + (lane&7)) * KST + (lane>>4)*8) * 2;
    const uint32_t b_off = ((wn*32  + ((lane>>4)&1)*8 + (lane&7)) * KST + ((lane>>3)&1)*8) * 2;

    auto load = [&](int bb, int k0) {
        cp16u(a_st0 + bb*ABUF, A + (size_t)ga0*lda + k0 + koff);
        cp16u(a_st1 + bb*ABUF, A + (size_t)ga1*lda + k0 + koff);
#pragma unroll
        for (int j = 0; j < BNT/64; j++)
            cp16u(b_st0 + j*64*(KST*2) + bb*BBUF,
                  Wt + (size_t)(n0 + (t>>2) + j*64)*K + k0 + koff);
    };
    load(0, 0);
    cpcommit();
    const int nch = K >> 5;
    for (int ch = 0; ch < nch; ch++) {
        int bb = ch & 1;
        if (ch + 1 < nch) { load(bb^1, (ch+1) << 5); cpcommit(); cpwait<1>(); }
        else cpwait<0>();
        __syncthreads();
#pragma unroll
        for (int ks = 0; ks < 2; ks++) {
            uint32_t af[MF][4], bfr[2][4];
#pragma unroll
            for (int mf = 0; mf < MF; mf++)
                ldsm4(af[mf], asb + bb*ABUF + a_off + mf*16*KST*2 + ks*32);
            ldsm4(bfr[0], bsb + bb*BBUF + b_off + ks*32);
            ldsm4(bfr[1], bsb + bb*BBUF + b_off + 16*KST*2 + ks*32);
#pragma unroll
            for (int mf = 0; mf < MF; mf++)
#pragma unroll
                for (int nf = 0; nf < 4; nf++)
                    mma16(acc[mf][nf], af[mf], &bfr[nf>>1][(nf&1)*2]);
        }
        __syncthreads();
    }
    // epilogue
#pragma unroll
    for (int mf = 0; mf < MF; mf++) {
#pragma unroll
        for (int half = 0; half < 2; half++) {
            int r = m0 + wm*WTM + mf*16 + (lane>>2) + half*8;
            unsigned char mm = (EPI == 2) ? mask[r] : 0;
#pragma unroll
            for (int nf = 0; nf < 4; nf++) {
                int c = n0 + wn*32 + nf*8 + (lane&3)*2;
                float v0 = acc[mf][nf][half*2], v1 = acc[mf][nf][half*2+1];
                if (EPI == 0) {
                    bf* Ob = (bf*)OutV + (size_t)dir*oz;
                    *(__nv_bfloat162*)(Ob + (size_t)r*ldo + c) =
                        __floats2bfloat162_rn(v0, v1);
                } else if (EPI == 1) {
                    float* Of = (float*)OutV + (size_t)dir*oz;
                    float2 f = {v0, v1};
                    *(float2*)(Of + (size_t)r*ldo + c) = f;
                } else {
                    float* Of = (float*)OutV;
                    v0 += bias[c]; v1 += bias[c+1];
                    if (mm) { v0 = 0.0f; v1 = 0.0f; }
                    float2 f = {v0, v1};
                    *(float2*)(Of + (size_t)r*ldo + c) = f;
                }
            }
        }
    }
}

// ---------------- conv1d as shifted-row bf16 GEMM (BN=128, pre-transposed weights) ----------------
__global__ __launch_bounds__(256, 2)
void conv_bf(const bf* __restrict__ In, const bf* __restrict__ Wl,
             const float* __restrict__ bias, float* __restrict__ Out) {
    constexpr int BNT = 128;
    __shared__ __align__(16) bf As[2][BM][KST];
    __shared__ __align__(16) bf Bs[2][BNT][KST];
    const int t = threadIdx.x, lane = t & 31, warp = t >> 5;
    const int wm = warp >> 2, wn = warp & 3;   // 2 x 4 warp grid, warp tile 64x32
    const int m0 = blockIdx.y * BM, n0 = blockIdx.x * BNT;

    float acc[4][4][4];
#pragma unroll
    for (int i = 0; i < 4; i++)
#pragma unroll
        for (int j = 0; j < 4; j++)
#pragma unroll
            for (int q = 0; q < 4; q++) acc[i][j][q] = 0.0f;

    const int lrowA = t >> 2;
    const int koff  = (t & 3) * 8;
    const int gr0 = m0 + lrowA, gr1 = m0 + lrowA + 64;
    const int l0 = gr0 & (SEQL-1), l1 = gr1 & (SEQL-1);

    uint32_t asb = (uint32_t)__cvta_generic_to_shared(&As[0][0][0]);
    uint32_t bsb = (uint32_t)__cvta_generic_to_shared(&Bs[0][0][0]);
    const int ABUF = BM*KST*2, BBUF = BNT*KST*2;
    const uint32_t a_st0 = asb + lrowA * (KST*2) + koff*2;
    const uint32_t a_st1 = a_st0 + 64 * (KST*2);
    const uint32_t b_st0 = bsb + (t >> 2) * (KST*2) + koff*2;
    const uint32_t a_off = ((wm*64 + ((lane>>3)&1)*8 + (lane&7)) * KST + (lane>>4)*8) * 2;
    const uint32_t b_off = ((wn*32 + ((lane>>4)&1)*8 + (lane&7)) * KST + ((lane>>3)&1)*8) * 2;

    auto load = [&](int bb, int ch) {
        int kk = ch >> 4, ci0 = (ch & 15) << 5;
        int sh = kk - 2;
        int v0 = (unsigned)(l0 + sh) < (unsigned)SEQL;
        int v1 = (unsigned)(l1 + sh) < (unsigned)SEQL;
        int rr0 = v0 ? gr0 + sh : gr0;
        int rr1 = v1 ? gr1 + sh : gr1;
        cp16z(a_st0 + bb*ABUF, In + (size_t)rr0*CH + ci0 + koff, v0);
        cp16z(a_st1 + bb*ABUF, In + (size_t)rr1*CH + ci0 + koff, v1);
#pragma unroll
        for (int j = 0; j < 2; j++)
            cp16u(b_st0 + j*64*(KST*2) + bb*BBUF,
                  Wl + ((size_t)kk*CH + n0 + (t>>2) + j*64)*CH + ci0 + koff);
    };
    load(0, 0);
    cpcommit();
    const int nch = KW * (CH/BK);   // 80
    for (int ch = 0; ch < nch; ch++) {
        int bb = ch & 1;
        if (ch + 1 < nch) { load(bb^1, ch+1); cpcommit(); cpwait<1>(); }
        else cpwait<0>();
        __syncthreads();
#pragma unroll
        for (int ks = 0; ks < 2; ks++) {
            uint32_t af[4][4], bfr[2][4];
#pragma unroll
            for (int mf = 0; mf < 4; mf++)
                ldsm4(af[mf], asb + bb*ABUF + a_off + mf*16*KST*2 + ks*32);
            ldsm4(bfr[0], bsb + bb*BBUF + b_off + ks*32);
            ldsm4(bfr[1], bsb + bb*BBUF + b_off + 16*KST*2 + ks*32);
#pragma unroll
            for (int mf = 0; mf < 4; mf++)
#pragma unroll
                for (int nf = 0; nf < 4; nf++)
                    mma16(acc[mf][nf], af[mf], &bfr[nf>>1][(nf&1)*2]);
        }
        __syncthreads();
    }
#pragma unroll
    for (int mf = 0; mf < 4; mf++) {
#pragma unroll
        for (int half = 0; half < 2; half++) {
            int r = m0 + wm*64 + mf*16 + (lane>>2) + half*8;
#pragma unroll
            for (int nf = 0; nf < 4; nf++) {
                int c = n0 + wn*32 + nf*8 + (lane&3)*2;
                float2 f = {acc[mf][nf][half*2] + bias[c],
                            acc[mf][nf][half*2+1] + bias[c+1]};
                *(float2*)(Out + (size_t)r*CH + c) = f;
            }
        }
    }
}

// ---------------- channel LayerNorm + LeakyReLU + mask ----------------
__global__ void ln_k(const float* __restrict__ In, const float* __restrict__ gamma,
                     const float* __restrict__ beta, const unsigned char* __restrict__ m,
                     bf* __restrict__ Out) {
    int row = blockIdx.x;
    int t = threadIdx.x;   // 128
    float v[4];
    float s = 0.0f;
#pragma unroll
    for (int i = 0; i < 4; i++) {
        v[i] = In[(size_t)row * CH + t + i * 128];
        s += v[i];
    }
    __shared__ float sm[4];
    for (int o = 16; o > 0; o >>= 1) s += __shfl_xor_sync(~0u, s, o);
    if ((t & 31) == 0) sm[t >> 5] = s;
    __syncthreads();
    float mean = (sm[0] + sm[1] + sm[2] + sm[3]) * (1.0f / CH);
    __syncthreads();
    float s2 = 0.0f;
#pragma unroll
    for (int i = 0; i < 4; i++) { float d = v[i] - mean; s2 += d * d; }
    for (int o = 16; o > 0; o >>= 1) s2 += __shfl_xor_sync(~0u, s2, o);
    if ((t & 31) == 0) sm[t >> 5] = s2;
    __syncthreads();
    float var = (sm[0] + sm[1] + sm[2] + sm[3]) * (1.0f / CH);
    float rstd = rsqrtf(var + 1e-5f);
    unsigned char mm = m[row];
#pragma unroll
    for (int i = 0; i < 4; i++) {
        int c = t + i * 128;
        float h = (v[i] - mean) * rstd * gamma[c] + beta[c];
        h = (h > 0.0f) ? h : 0.2f * h;
        if (mm) h = 0.0f;
        Out[(size_t)row * CH + c] = __float2bfloat16(h);
    }
}

// ---------------- causal depthwise conv + SiLU (both dirs in one launch) ----------------
__global__ void dwconv_k(const bf* __restrict__ xz,
                         const float* __restrict__ cwf, const float* __restrict__ cbf,
                         const float* __restrict__ cwb, const float* __restrict__ cbb,
                         bf* __restrict__ out) {
    int idx = blockIdx.x * blockDim.x + threadIdx.x;
    if (idx >= 2*BL*DI) return;
    int dir = idx >> 22;                     // BL*DI = 2^22
    int r = idx & ((1 << 22) - 1);
    int d = r & (DI - 1);
    int row = r >> 10;
    int l = row & (SEQL - 1);
    const bf* xzd = xz + ((size_t)dir << 23);   // BL*XZW = 2^23
    const float* cw = dir ? cwb : cwf;
    float acc = (dir ? cbb : cbf)[d];
#pragma unroll
    for (int k = 0; k < 4; k++) {
        int lp = l - 3 + k;
        if (lp >= 0)
            acc = fmaf(cw[d*4 + k], __bfloat162float(xzd[(size_t)(row - l + lp)*XZW + d]), acc);
    }
    out[((size_t)dir << 22) + r] = __float2bfloat16(siluf(acc));
}

// ---------------- delta = softplus(xdbc[:, :32] @ dt_w.T + dt_b), both dirs ----------------
__global__ __launch_bounds__(256)
void dt_k(const float* __restrict__ xdbc,
          const float* __restrict__ wf, const float* __restrict__ dbf,
          const float* __restrict__ wb, const float* __restrict__ dbb,
          float* __restrict__ delta) {
    int dir = blockIdx.z;
    xdbc  += (size_t)dir * BL * 64;
    delta += (size_t)dir * BL * DI;
    const float* dt_w = dir ? wb : wf;
    const float* dt_b = dir ? dbb : dbf;
    __shared__ float xs[32][32];
    int t = threadIdx.x;
    int d0 = blockIdx.x * 256, m0 = blockIdx.y * 32;
#pragma unroll
    for (int i = 0; i < 4; i++) {
        int idx = t + i * 256;
        xs[idx >> 5][idx & 31] = xdbc[(size_t)(m0 + (idx >> 5)) * 64 + (idx & 31)];
    }
    int d = d0 + t;
    float4 wr[8];
#pragma unroll
    for (int j = 0; j < 8; j++) wr[j] = *(const float4*)(dt_w + (size_t)d*DTR + j*4);
    float b = dt_b[d];
    __syncthreads();
#pragma unroll 4
    for (int row = 0; row < 32; row++) {
        float acc = b;
#pragma unroll
        for (int j = 0; j < 8; j++) {
            float4 x4 = *(const float4*)&xs[row][j*4];
            acc = fmaf(wr[j].x, x4.x, acc);
            acc = fmaf(wr[j].y, x4.y, acc);
            acc = fmaf(wr[j].z, x4.z, acc);
            acc = fmaf(wr[j].w, x4.w, acc);
        }
        delta[(size_t)(m0 + row) * DI + d] = softplusf(acc);
    }
}

// ---------------- selective scan + gate (both dirs in one launch) ----------------
__global__ void scan_k(const float* __restrict__ delta, const bf* __restrict__ u,
                       const float* __restrict__ xdbc, const bf* __restrict__ xz,
                       const float* __restrict__ Af, const float* __restrict__ Df,
                       const float* __restrict__ Ab, const float* __restrict__ Db,
                       bf* __restrict__ y) {
    int dir = blockIdx.z;
    delta += (size_t)dir * BL * DI;
    u     += (size_t)dir * BL * DI;
    xdbc  += (size_t)dir * BL * 64;
    xz    += (size_t)dir * BL * XZW;
    y     += (size_t)dir * BL * DI;
    const float* A_log = dir ? Ab : Af;
    const float* Dv    = dir ? Db : Df;
    int t = threadIdx.x;            // 256
    int n = t & 15, dd = t >> 4;
    int d = blockIdx.x * 16 + dd;
    int b = blockIdx.y;
    float a  = -__expf(A_log[d * DS + n]);
    float Dd = Dv[d];
    float h = 0.0f;
    int base = b * SEQL;
    float de = delta[(size_t)base * DI + d];
    float uu = __bfloat162float(u[(size_t)base * DI + d]);
    float Bv = xdbc[base * 64 + DTR + n];
    float Cv = xdbc[base * 64 + DTR + DS + n];
    for (int l = 0; l < SEQL; l++) {
        int row = base + l;
        int rn = (l + 1 < SEQL) ? row + 1 : row;
        float de_n = delta[(size_t)rn * DI + d];
        float uu_n = __bfloat162float(u[(size_t)rn * DI + d]);
        float Bv_n = xdbc[rn * 64 + DTR + n];
        float Cv_n = xdbc[rn * 64 + DTR + DS + n];
        float dA = __expf(de * a);
        h = fmaf(dA, h, de * Bv * uu);
        float c = h * Cv;
        c += __shfl_xor_sync(0xffffffffu, c, 1, 16);
        c += __shfl_xor_sync(0xffffffffu, c, 2, 16);
        c += __shfl_xor_sync(0xffffffffu, c, 4, 16);
        c += __shfl_xor_sync(0xffffffffu, c, 8, 16);
        if (n == 0) {
            float z = __bfloat162float(xz[(size_t)row * XZW + DI + d]);
            y[(size_t)row * DI + d] = __float2bfloat16((c + uu * Dd) * siluf(z));
        }
        de = de_n; uu = uu_n; Bv = Bv_n; Cv = Cv_n;
    }
}

// ---------------- launch ----------------
template <typename T>
static T* symp(const void* sym) {
    void* p = nullptr;
    cudaGetSymbolAddress(&p, sym);
    return (T*)p;
}

extern "C" void kernel_launch(void* const* d_in, const int* in_sizes, int n_in,
                              void* d_out, int out_size) {
    const int*           x      = (const int*)d_in[0];
    const unsigned char* m      = (const unsigned char*)d_in[2];
    const float*         emb    = (const float*)d_in[3];
    const float*         conv_w = (const float*)d_in[4];
    const float*         conv_b = (const float*)d_in[5];
    const float*         ln_g   = (const float*)d_in[6];
    const float*         ln_b   = (const float*)d_in[7];
    const float*         proj_b = (const float*)d_in[9];
    float* out = (float*)d_out;

    bf*    h    = symp<bf>(g_h);
    float* tmp  = symp<float>(g_tmp);
    bf*    xz   = symp<bf>(g_xz);
    bf*    u    = symp<bf>(g_u);
    float* dl   = symp<float>(g_delta);
    float* xdbc = symp<float>(g_xdbc);
    bf*    y    = symp<bf>(g_y);
    bf*    comb = symp<bf>(g_comb);
    bf*    cwt  = symp<bf>(g_cwt);
    bf*    inw  = symp<bf>(g_inw);
    bf*    xw   = symp<bf>(g_xw);
    bf*    outw = symp<bf>(g_outw);
    bf*    prw  = symp<bf>(g_projw);

    // 1: conv weight transpose, 2: all fp32->bf16 weight conversions
    convT_k<<<3*CH, 256>>>(conv_w);
    {
        CvtP p;
        p.s[0] = (const float*)d_in[10];  p.d[0] = inw;
        p.s[1] = (const float*)d_in[19];  p.d[1] = inw + (size_t)XZW*CH;
        p.s[2] = (const float*)d_in[13];  p.d[2] = xw;
        p.s[3] = (const float*)d_in[22];  p.d[3] = xw + (size_t)64*DI;
        p.s[4] = (const float*)d_in[18];  p.d[4] = outw;
        p.s[5] = (const float*)d_in[27];  p.d[5] = outw + (size_t)CH*DI;
        p.s[6] = (const float*)d_in[8];   p.d[6] = prw;
        f2bf_all<<<3712, 256>>>(p);
    }
    // 3: embedding
    embed_k<<<(BL*CH + 255)/256, 256>>>(x, emb, h);

    // 4-9: conv stack (launch #6 = conv layer 1 for ncu capture)
    for (int layer = 0; layer < 3; layer++) {
        conv_bf<<<dim3(CH/128, BL/BM), 256>>>(
            h, cwt + (size_t)layer*KW*CH*CH, conv_b + layer*CH, tmp);
        ln_k<<<BL, 128>>>(tmp, ln_g + layer*CH, ln_b + layer*CH, m, h);
    }

    // mamba stages, both directions batched via blockIdx.z
    const float* mcwf = (const float*)d_in[11];
    const float* mcbf = (const float*)d_in[12];
    const float* mcwb = (const float*)d_in[20];
    const float* mcbb = (const float*)d_in[21];
    const float* dtwf = (const float*)d_in[14];
    const float* dtbf = (const float*)d_in[15];
    const float* dtwb = (const float*)d_in[23];
    const float* dtbb = (const float*)d_in[24];
    const float* Alf  = (const float*)d_in[16];
    const float* Dvf  = (const float*)d_in[17];
    const float* Alb  = (const float*)d_in[25];
    const float* Dvb  = (const float*)d_in[26];

    // in-proj: xz[dir] = h(rev if dir) @ inw[dir]^T
    gemm_bf<128, 0><<<dim3(XZW/128, BL/BM, 2), 256>>>(
        h, inw, nullptr, xz, CH, CH, XZW, 1, nullptr,
        0, (size_t)XZW*CH, (size_t)BL*XZW);
    // depthwise conv + silu
    dwconv_k<<<(2*BL*DI + 255)/256, 256>>>(xz, mcwf, mcbf, mcwb, mcbb, u);
    // xdbc = u @ xw^T
    gemm_bf<64, 1><<<dim3(1, BL/BM, 2), 256>>>(
        u, xw, nullptr, xdbc, DI, DI, 64, 0, nullptr,
        (size_t)BL*DI, (size_t)64*DI, (size_t)BL*64);
    // delta
    dt_k<<<dim3(DI/256, BL/32, 2), 256>>>(xdbc, dtwf, dtbf, dtwb, dtbb, dl);
    // selective scan + gate
    scan_k<<<dim3(DI/16, BATCH, 2), 256>>>(dl, u, xdbc, xz, Alf, Dvf, Alb, Dvb, y);
    // out-proj -> comb halves
    gemm_bf<128, 0><<<dim3(CH/128, BL/BM, 2), 256>>>(
        y, outw, nullptr, comb, DI, DI, 2*CH, 0, nullptr,
        (size_t)BL*DI, (size_t)CH*DI, (size_t)CH);

    // final projection + bias + mask
    gemm_bf<64, 2><<<dim3(CH/64, BL/BM, 1), 256>>>(
        comb, prw, proj_b, out, 2*CH, 2*CH, CH, 0, m, 0, 0, 0);
}